// round 1
// baseline (speedup 1.0000x reference)
#include <cuda_runtime.h>
#include <math.h>

#define NN 10000
#define EE 160000

// ---------------- scratch (device globals; no allocations allowed) ----------
__device__ float g_Q[NN * 64];
__device__ float g_K[NN * 64];
__device__ float g_V[NN * 64];
__device__ float g_MA[NN * 512];
__device__ float g_MB[NN * 512];
__device__ float g_deginv[NN];
__device__ float g_norm[EE];
__device__ int   g_cnt[NN];
__device__ int   g_ptr[NN + 1];
__device__ int   g_wp[NN];
__device__ int   g_eidx[EE];

// ---------------- small setup kernels ---------------------------------------
__global__ void k_zero() {
    int i = blockIdx.x * blockDim.x + threadIdx.x;
    if (i < NN) g_cnt[i] = 0;
}

__global__ void k_count(const int* __restrict__ col) {
    int e = blockIdx.x * blockDim.x + threadIdx.x;
    if (e < EE) atomicAdd(&g_cnt[col[e]], 1);
}

// single-block exclusive scan of g_cnt -> g_ptr / g_wp
__global__ void k_scan() {
    __shared__ int s[1024];
    int t = threadIdx.x;
    const int CH = (NN + 1023) / 1024;  // 10
    int start = t * CH;
    int sum = 0;
    for (int i = 0; i < CH; i++) {
        int idx = start + i;
        if (idx < NN) sum += g_cnt[idx];
    }
    s[t] = sum;
    __syncthreads();
    for (int off = 1; off < 1024; off <<= 1) {
        int v = (t >= off) ? s[t - off] : 0;
        __syncthreads();
        s[t] += v;
        __syncthreads();
    }
    int run = (t == 0) ? 0 : s[t - 1];
    for (int i = 0; i < CH; i++) {
        int idx = start + i;
        if (idx < NN) {
            g_ptr[idx] = run;
            g_wp[idx]  = run;
            run += g_cnt[idx];
        }
    }
    if (t == 0) g_ptr[NN] = s[1023];
}

__global__ void k_deginv() {
    int i = blockIdx.x * blockDim.x + threadIdx.x;
    if (i < NN) {
        int c = g_cnt[i];
        g_deginv[i] = (c > 0) ? rsqrtf((float)c) : 0.0f;
    }
}

__global__ void k_place(const int* __restrict__ col) {
    int e = blockIdx.x * blockDim.x + threadIdx.x;
    if (e < EE) {
        int c = col[e];
        int p = atomicAdd(&g_wp[c], 1);
        g_eidx[p] = e;
    }
}

// sort each bucket ascending -> deterministic accumulation order
__global__ void k_sortbuckets() {
    int n = blockIdx.x * blockDim.x + threadIdx.x;
    if (n >= NN) return;
    int b = g_ptr[n], e2 = g_ptr[n + 1];
    for (int i = b + 1; i < e2; i++) {
        int v = g_eidx[i];
        int j = i - 1;
        while (j >= b && g_eidx[j] > v) {
            g_eidx[j + 1] = g_eidx[j];
            j--;
        }
        g_eidx[j + 1] = v;
    }
}

__global__ void k_norm(const int* __restrict__ row, const int* __restrict__ col,
                       const float* __restrict__ ew) {
    int e = blockIdx.x * blockDim.x + threadIdx.x;
    if (e < EE) g_norm[e] = g_deginv[row[e]] * g_deginv[col[e]] * ew[e];
}

// ---------------- Q/K/V GEMM + hidden init ----------------------------------
// 16 nodes per block, 256 threads; each thread owns (col c) x (4 nodes)
__global__ void k_qkv(const float* __restrict__ x,
                      const float* __restrict__ Wq, const float* __restrict__ bq,
                      const float* __restrict__ Wk, const float* __restrict__ bk,
                      const float* __restrict__ Wv, const float* __restrict__ bv,
                      const float* __restrict__ hopwise, float* __restrict__ out) {
    __shared__ float sx[16 * 64];
    int n0 = blockIdx.x * 16;
    for (int idx = threadIdx.x; idx < 16 * 64; idx += 256)
        sx[idx] = x[(n0 + (idx >> 6)) * 64 + (idx & 63)];
    __syncthreads();

    int c = threadIdx.x & 63;
    int g = threadIdx.x >> 6;  // 0..3
    float aq[4] = {0, 0, 0, 0}, ak[4] = {0, 0, 0, 0}, av[4] = {0, 0, 0, 0};
#pragma unroll 4
    for (int k = 0; k < 64; k++) {
        float wq = Wq[k * 64 + c];
        float wk = Wk[k * 64 + c];
        float wv = Wv[k * 64 + c];
#pragma unroll
        for (int p = 0; p < 4; p++) {
            float xv = sx[(g + 4 * p) * 64 + k];
            aq[p] += xv * wq;
            ak[p] += xv * wk;
            av[p] += xv * wv;
        }
    }
    float hw0 = hopwise[0];
    float bqc = bq[c], bkc = bk[c], bvc = bv[c];
#pragma unroll
    for (int p = 0; p < 4; p++) {
        int n = n0 + g + 4 * p;
        g_Q[n * 64 + c] = fmaxf(aq[p] + bqc, 0.0f);
        g_K[n * 64 + c] = ak[p] + bkc;
        float v = av[p] + bvc;
        g_V[n * 64 + c] = v;
        out[n * 64 + c] = hw0 * v;  // hidden = hopwise[0] * V
    }
}

// ---------------- hop 0: M0[col] = sum_e norm * outer(relu(K[row]+ef), V[row])
// one warp per destination node; lane owns 16 of the 512 M entries
__global__ void k_hop0(const int* __restrict__ rowArr, const float* __restrict__ ef) {
    int warp = (blockIdx.x * blockDim.x + threadIdx.x) >> 5;
    if (warp >= NN) return;
    int lane = threadIdx.x & 31;
    int h8 = (lane >> 2) << 3;        // h*8
    int i0 = (lane & 3) * 2;          // first of two i values

    float acc[16];
#pragma unroll
    for (int t = 0; t < 16; t++) acc[t] = 0.0f;

    int beg = g_ptr[warp], end = g_ptr[warp + 1];
    for (int base = beg; base < end; base += 32) {
        int k = base + lane;
        int e = 0, r = 0;
        float w = 0.0f;
        if (k < end) {
            e = g_eidx[k];
            r = rowArr[e];
            w = g_norm[e];
        }
        int cnt = min(32, end - base);
        for (int t = 0; t < cnt; t++) {
            int   re = __shfl_sync(0xffffffffu, r, t);
            int   ee = __shfl_sync(0xffffffffu, e, t);
            float we = __shfl_sync(0xffffffffu, w, t);

            float2 kk = *(const float2*)(g_K + re * 64 + h8 + i0);
            float2 ev = *(const float2*)(ef + ee * 64 + h8 + i0);
            float kj0 = fmaxf(kk.x + ev.x, 0.0f) * we;
            float kj1 = fmaxf(kk.y + ev.y, 0.0f) * we;
            float4 va = *(const float4*)(g_V + re * 64 + h8);
            float4 vb = *(const float4*)(g_V + re * 64 + h8 + 4);

            acc[0]  += kj0 * va.x;  acc[1]  += kj0 * va.y;
            acc[2]  += kj0 * va.z;  acc[3]  += kj0 * va.w;
            acc[4]  += kj0 * vb.x;  acc[5]  += kj0 * vb.y;
            acc[6]  += kj0 * vb.z;  acc[7]  += kj0 * vb.w;
            acc[8]  += kj1 * va.x;  acc[9]  += kj1 * va.y;
            acc[10] += kj1 * va.z;  acc[11] += kj1 * va.w;
            acc[12] += kj1 * vb.x;  acc[13] += kj1 * vb.y;
            acc[14] += kj1 * vb.z;  acc[15] += kj1 * vb.w;
        }
    }
    float4* dst = (float4*)(g_MA + warp * 512 + lane * 16);
    dst[0] = make_float4(acc[0], acc[1], acc[2], acc[3]);
    dst[1] = make_float4(acc[4], acc[5], acc[6], acc[7]);
    dst[2] = make_float4(acc[8], acc[9], acc[10], acc[11]);
    dst[3] = make_float4(acc[12], acc[13], acc[14], acc[15]);
}

// ---------------- hops 1..: Mdst[col] = sum_e norm * Msrc[row] ---------------
// one warp per destination node; 16 floats (4x float4) per lane
__global__ void k_prop(int dir, const int* __restrict__ rowArr) {
    const float* __restrict__ Msrc = dir ? g_MB : g_MA;
    float* __restrict__ Mdst       = dir ? g_MA : g_MB;
    int warp = (blockIdx.x * blockDim.x + threadIdx.x) >> 5;
    if (warp >= NN) return;
    int lane = threadIdx.x & 31;

    float4 a0 = make_float4(0, 0, 0, 0), a1 = a0, a2 = a0, a3 = a0;

    int beg = g_ptr[warp], end = g_ptr[warp + 1];
    for (int base = beg; base < end; base += 32) {
        int k = base + lane;
        int r = 0;
        float w = 0.0f;
        if (k < end) {
            int e = g_eidx[k];
            r = rowArr[e];
            w = g_norm[e];
        }
        int cnt = min(32, end - base);
        for (int t = 0; t < cnt; t++) {
            int   re = __shfl_sync(0xffffffffu, r, t);
            float we = __shfl_sync(0xffffffffu, w, t);
            const float4* mp = (const float4*)(Msrc + re * 512 + lane * 16);
            float4 m0 = mp[0], m1 = mp[1], m2 = mp[2], m3 = mp[3];
            a0.x += we * m0.x; a0.y += we * m0.y; a0.z += we * m0.z; a0.w += we * m0.w;
            a1.x += we * m1.x; a1.y += we * m1.y; a1.z += we * m1.z; a1.w += we * m1.w;
            a2.x += we * m2.x; a2.y += we * m2.y; a2.z += we * m2.z; a2.w += we * m2.w;
            a3.x += we * m3.x; a3.y += we * m3.y; a3.z += we * m3.z; a3.w += we * m3.w;
        }
    }
    float4* dst = (float4*)(Mdst + warp * 512 + lane * 16);
    dst[0] = a0; dst[1] = a1; dst[2] = a2; dst[3] = a3;
}

// ---------------- H = Q.M per (node, head), normalize, accumulate -----------
__global__ void k_hupd(int which, const float* __restrict__ hopwise, int hop,
                       float* __restrict__ out) {
    const float* __restrict__ M = which ? g_MB : g_MA;
    int gid = blockIdx.x * blockDim.x + threadIdx.x;
    if (gid >= NN * 8) return;
    int n = gid >> 3, h = gid & 7;

    const float4* qp = (const float4*)(g_Q + n * 64 + h * 8);
    float4 q0 = qp[0], q1 = qp[1];
    float qa[8] = {q0.x, q0.y, q0.z, q0.w, q1.x, q1.y, q1.z, q1.w};

    const float4* Mv = (const float4*)(M + n * 512 + h * 64);
    float4 H0 = make_float4(0, 0, 0, 0), H1 = H0;
#pragma unroll
    for (int i = 0; i < 8; i++) {
        float qi = qa[i];
        float4 m0 = Mv[2 * i], m1 = Mv[2 * i + 1];
        H0.x += qi * m0.x; H0.y += qi * m0.y; H0.z += qi * m0.z; H0.w += qi * m0.w;
        H1.x += qi * m1.x; H1.y += qi * m1.y; H1.z += qi * m1.z; H1.w += qi * m1.w;
    }
    float ss = H0.x * H0.x + H0.y * H0.y + H0.z * H0.z + H0.w * H0.w +
               H1.x * H1.x + H1.y * H1.y + H1.z * H1.z + H1.w * H1.w;
    float nrm = sqrtf(ss * 0.125f);
    float sc = (nrm > 1.0f) ? (1.0f / nrm) : 1.0f;
    float c = hopwise[hop] * sc;

    float4* op = (float4*)(out + n * 64 + h * 8);
    float4 o0 = op[0], o1 = op[1];
    o0.x += c * H0.x; o0.y += c * H0.y; o0.z += c * H0.z; o0.w += c * H0.w;
    o1.x += c * H1.x; o1.y += c * H1.y; o1.z += c * H1.z; o1.w += c * H1.w;
    op[0] = o0; op[1] = o1;
}

// ---------------- launch -----------------------------------------------------
extern "C" void kernel_launch(void* const* d_in, const int* in_sizes, int n_in,
                              void* d_out, int out_size) {
    const float* x  = (const float*)d_in[0];
    const int*   ei = (const int*)d_in[1];
    const float* ef = (const float*)d_in[2];
    const float* ew = (const float*)d_in[3];
    const float* Wq = (const float*)d_in[4];
    const float* bq = (const float*)d_in[5];
    const float* Wk = (const float*)d_in[6];
    const float* bk = (const float*)d_in[7];
    const float* Wv = (const float*)d_in[8];
    const float* bv = (const float*)d_in[9];
    const float* hw = (const float*)d_in[10];
    const int* row = ei;
    const int* col = ei + EE;
    float* out = (float*)d_out;

    k_zero<<<(NN + 255) / 256, 256>>>();
    k_count<<<(EE + 255) / 256, 256>>>(col);
    k_scan<<<1, 1024>>>();
    k_deginv<<<(NN + 255) / 256, 256>>>();
    k_place<<<(EE + 255) / 256, 256>>>(col);
    k_sortbuckets<<<(NN + 255) / 256, 256>>>();
    k_norm<<<(EE + 255) / 256, 256>>>(row, col, ew);

    k_qkv<<<NN / 16, 256>>>(x, Wq, bq, Wk, bk, Wv, bv, hw, out);

    k_hop0<<<(NN * 32) / 256, 256>>>(row, ef);          // -> g_MA
    k_hupd<<<(NN * 8 + 255) / 256, 256>>>(0, hw, 1, out);

    k_prop<<<(NN * 32) / 256, 256>>>(0, row);           // MA -> MB
    k_hupd<<<(NN * 8 + 255) / 256, 256>>>(1, hw, 2, out);

    k_prop<<<(NN * 32) / 256, 256>>>(1, row);           // MB -> MA
    k_hupd<<<(NN * 8 + 255) / 256, 256>>>(0, hw, 3, out);
}

// round 2
// speedup vs baseline: 1.8854x; 1.8854x over previous
#include <cuda_runtime.h>
#include <cuda_fp16.h>
#include <math.h>

#define NN 10000
#define EE 160000

// ---------------- scratch (device globals; no allocations allowed) ----------
__device__ float g_Q[NN * 64];
__device__ float g_K[NN * 64];
__device__ float g_V[NN * 64];
__device__ uint4 g_MA4[NN * 64];   // NN x 512 halfs (16B-aligned)
__device__ uint4 g_MB4[NN * 64];
__device__ float g_deginv[NN];
__device__ int   g_cnt[NN];
__device__ int   g_ptr[NN + 1];
__device__ int   g_wp[NN];
__device__ int   g_eidx[EE];   // edge id, sorted by destination then edge id
__device__ int   g_src[EE];    // source node per sorted position
__device__ float g_wt[EE];     // norm weight per sorted position

// ---------------- setup ------------------------------------------------------
__global__ void k_zero() {
    int i = blockIdx.x * blockDim.x + threadIdx.x;
    if (i < NN) g_cnt[i] = 0;
}

__global__ void k_count(const int* __restrict__ col) {
    int e = blockIdx.x * blockDim.x + threadIdx.x;
    if (e < EE) atomicAdd(&g_cnt[col[e]], 1);
}

// single-block exclusive scan of g_cnt -> g_ptr / g_wp ; also deginv
__global__ void k_scan() {
    __shared__ int s[1024];
    int t = threadIdx.x;
    const int CH = (NN + 1023) / 1024;
    int start = t * CH;
    int sum = 0;
    for (int i = 0; i < CH; i++) {
        int idx = start + i;
        if (idx < NN) sum += g_cnt[idx];
    }
    s[t] = sum;
    __syncthreads();
    for (int off = 1; off < 1024; off <<= 1) {
        int v = (t >= off) ? s[t - off] : 0;
        __syncthreads();
        s[t] += v;
        __syncthreads();
    }
    int run = (t == 0) ? 0 : s[t - 1];
    for (int i = 0; i < CH; i++) {
        int idx = start + i;
        if (idx < NN) {
            int c = g_cnt[idx];
            g_ptr[idx] = run;
            g_wp[idx]  = run;
            g_deginv[idx] = (c > 0) ? rsqrtf((float)c) : 0.0f;
            run += c;
        }
    }
    if (t == 0) g_ptr[NN] = s[1023];
}

__global__ void k_place(const int* __restrict__ col) {
    int e = blockIdx.x * blockDim.x + threadIdx.x;
    if (e < EE) {
        int c = col[e];
        int p = atomicAdd(&g_wp[c], 1);
        g_eidx[p] = e;
    }
}

// sort each bucket ascending -> deterministic accumulation order
__global__ void k_sortbuckets() {
    int n = blockIdx.x * blockDim.x + threadIdx.x;
    if (n >= NN) return;
    int b = g_ptr[n], e2 = g_ptr[n + 1];
    for (int i = b + 1; i < e2; i++) {
        int v = g_eidx[i];
        int j = i - 1;
        while (j >= b && g_eidx[j] > v) {
            g_eidx[j + 1] = g_eidx[j];
            j--;
        }
        g_eidx[j + 1] = v;
    }
}

// per sorted position: source node + norm weight
__global__ void k_gather(const int* __restrict__ row, const int* __restrict__ col,
                         const float* __restrict__ ew) {
    int p = blockIdx.x * blockDim.x + threadIdx.x;
    if (p >= EE) return;
    int e = g_eidx[p];
    int r = row[e];
    int c = col[e];
    g_src[p] = r;
    g_wt[p]  = g_deginv[r] * g_deginv[c] * ew[e];
}

// ---------------- Q/K/V GEMM + hidden init ----------------------------------
__global__ void k_qkv(const float* __restrict__ x,
                      const float* __restrict__ Wq, const float* __restrict__ bq,
                      const float* __restrict__ Wk, const float* __restrict__ bk,
                      const float* __restrict__ Wv, const float* __restrict__ bv,
                      const float* __restrict__ hopwise, float* __restrict__ out) {
    __shared__ float sx[16 * 64];
    int n0 = blockIdx.x * 16;
    for (int idx = threadIdx.x; idx < 16 * 64; idx += 256)
        sx[idx] = x[(n0 + (idx >> 6)) * 64 + (idx & 63)];
    __syncthreads();

    int c = threadIdx.x & 63;
    int g = threadIdx.x >> 6;
    float aq[4] = {0, 0, 0, 0}, ak[4] = {0, 0, 0, 0}, av[4] = {0, 0, 0, 0};
#pragma unroll 4
    for (int k = 0; k < 64; k++) {
        float wq = Wq[k * 64 + c];
        float wk = Wk[k * 64 + c];
        float wv = Wv[k * 64 + c];
#pragma unroll
        for (int p = 0; p < 4; p++) {
            float xv = sx[(g + 4 * p) * 64 + k];
            aq[p] += xv * wq;
            ak[p] += xv * wk;
            av[p] += xv * wv;
        }
    }
    float hw0 = hopwise[0];
    float bqc = bq[c], bkc = bk[c], bvc = bv[c];
#pragma unroll
    for (int p = 0; p < 4; p++) {
        int n = n0 + g + 4 * p;
        g_Q[n * 64 + c] = fmaxf(aq[p] + bqc, 0.0f);
        g_K[n * 64 + c] = ak[p] + bkc;
        float v = av[p] + bvc;
        g_V[n * 64 + c] = v;
        out[n * 64 + c] = hw0 * v;
    }
}

// ---------------- fused epilogue: H = Q.M, normalize, out += hw*H ------------
// acc layout: lane owns h = lane>>2, i = (lane&3)*2 + {0,1}, all j (8).
// acc[0..7] = j for i0, acc[8..15] = j for i0+1.
__device__ __forceinline__ void h_epilogue(int n, int lane, const float* acc,
                                           float hw, float* __restrict__ out) {
    int h = lane >> 3 == 0 ? (lane >> 2) : (lane >> 2);  // h = lane>>2
    h = lane >> 2;
    float2 q = *(const float2*)(g_Q + n * 64 + h * 8 + (lane & 3) * 2);
    float Hp[8];
#pragma unroll
    for (int j = 0; j < 8; j++) Hp[j] = q.x * acc[j] + q.y * acc[8 + j];
#pragma unroll
    for (int off = 1; off < 4; off <<= 1) {
#pragma unroll
        for (int j = 0; j < 8; j++)
            Hp[j] += __shfl_xor_sync(0xffffffffu, Hp[j], off);
    }
    float ss = 0.f;
#pragma unroll
    for (int j = 0; j < 8; j++) ss += Hp[j] * Hp[j];
    float nrm = sqrtf(ss * 0.125f);
    float sc = (nrm > 1.0f) ? (1.0f / nrm) : 1.0f;
    float c = hw * sc;
    if ((lane & 3) == 0) {
        float4* op = (float4*)(out + n * 64 + h * 8);
        float4 o0 = op[0], o1 = op[1];
        o0.x += c * Hp[0]; o0.y += c * Hp[1]; o0.z += c * Hp[2]; o0.w += c * Hp[3];
        o1.x += c * Hp[4]; o1.y += c * Hp[5]; o1.z += c * Hp[6]; o1.w += c * Hp[7];
        op[0] = o0; op[1] = o1;
    }
}

__device__ __forceinline__ void acc8(float* a, uint4 A, float w) {
    const __half2* h = (const __half2*)&A;
#pragma unroll
    for (int q = 0; q < 4; q++) {
        float2 f = __half22float2(h[q]);
        a[2 * q]     += w * f.x;
        a[2 * q + 1] += w * f.y;
    }
}

// ---------------- hop 0 + fused H-update -------------------------------------
__global__ void __launch_bounds__(256) k_hop0(const float* __restrict__ ef,
                                              const float* __restrict__ hopwise,
                                              float* __restrict__ out) {
    int warp = (blockIdx.x * blockDim.x + threadIdx.x) >> 5;
    if (warp >= NN) return;
    int lane = threadIdx.x & 31;
    int h8 = (lane >> 2) << 3;
    int i0 = (lane & 3) * 2;

    float acc[16];
#pragma unroll
    for (int t = 0; t < 16; t++) acc[t] = 0.0f;

    int beg = g_ptr[warp], end = g_ptr[warp + 1];
    int p = beg;
    for (; p + 2 <= end; p += 2) {
        int e0 = g_eidx[p], e1 = g_eidx[p + 1];
        int r0 = g_src[p],  r1 = g_src[p + 1];
        float w0 = g_wt[p], w1 = g_wt[p + 1];
        float2 k0 = *(const float2*)(g_K + r0 * 64 + h8 + i0);
        float2 f0 = *(const float2*)(ef + (size_t)e0 * 64 + h8 + i0);
        float4 va0 = *(const float4*)(g_V + r0 * 64 + h8);
        float4 vb0 = *(const float4*)(g_V + r0 * 64 + h8 + 4);
        float2 k1 = *(const float2*)(g_K + r1 * 64 + h8 + i0);
        float2 f1 = *(const float2*)(ef + (size_t)e1 * 64 + h8 + i0);
        float4 va1 = *(const float4*)(g_V + r1 * 64 + h8);
        float4 vb1 = *(const float4*)(g_V + r1 * 64 + h8 + 4);

        float a0 = fmaxf(k0.x + f0.x, 0.0f) * w0;
        float a1 = fmaxf(k0.y + f0.y, 0.0f) * w0;
        acc[0]  += a0 * va0.x; acc[1]  += a0 * va0.y; acc[2]  += a0 * va0.z; acc[3]  += a0 * va0.w;
        acc[4]  += a0 * vb0.x; acc[5]  += a0 * vb0.y; acc[6]  += a0 * vb0.z; acc[7]  += a0 * vb0.w;
        acc[8]  += a1 * va0.x; acc[9]  += a1 * va0.y; acc[10] += a1 * va0.z; acc[11] += a1 * va0.w;
        acc[12] += a1 * vb0.x; acc[13] += a1 * vb0.y; acc[14] += a1 * vb0.z; acc[15] += a1 * vb0.w;

        float b0 = fmaxf(k1.x + f1.x, 0.0f) * w1;
        float b1 = fmaxf(k1.y + f1.y, 0.0f) * w1;
        acc[0]  += b0 * va1.x; acc[1]  += b0 * va1.y; acc[2]  += b0 * va1.z; acc[3]  += b0 * va1.w;
        acc[4]  += b0 * vb1.x; acc[5]  += b0 * vb1.y; acc[6]  += b0 * vb1.z; acc[7]  += b0 * vb1.w;
        acc[8]  += b1 * va1.x; acc[9]  += b1 * va1.y; acc[10] += b1 * va1.z; acc[11] += b1 * va1.w;
        acc[12] += b1 * vb1.x; acc[13] += b1 * vb1.y; acc[14] += b1 * vb1.z; acc[15] += b1 * vb1.w;
    }
    for (; p < end; p++) {
        int e0 = g_eidx[p];
        int r0 = g_src[p];
        float w0 = g_wt[p];
        float2 k0 = *(const float2*)(g_K + r0 * 64 + h8 + i0);
        float2 f0 = *(const float2*)(ef + (size_t)e0 * 64 + h8 + i0);
        float4 va0 = *(const float4*)(g_V + r0 * 64 + h8);
        float4 vb0 = *(const float4*)(g_V + r0 * 64 + h8 + 4);
        float a0 = fmaxf(k0.x + f0.x, 0.0f) * w0;
        float a1 = fmaxf(k0.y + f0.y, 0.0f) * w0;
        acc[0]  += a0 * va0.x; acc[1]  += a0 * va0.y; acc[2]  += a0 * va0.z; acc[3]  += a0 * va0.w;
        acc[4]  += a0 * vb0.x; acc[5]  += a0 * vb0.y; acc[6]  += a0 * vb0.z; acc[7]  += a0 * vb0.w;
        acc[8]  += a1 * va0.x; acc[9]  += a1 * va0.y; acc[10] += a1 * va0.z; acc[11] += a1 * va0.w;
        acc[12] += a1 * vb0.x; acc[13] += a1 * vb0.y; acc[14] += a1 * vb0.z; acc[15] += a1 * vb0.w;
    }

    // store M (fp16)
    uint4 o0, o1;
    __half2* ho0 = (__half2*)&o0;
    __half2* ho1 = (__half2*)&o1;
#pragma unroll
    for (int q = 0; q < 4; q++) {
        ho0[q] = __float22half2_rn(make_float2(acc[2 * q], acc[2 * q + 1]));
        ho1[q] = __float22half2_rn(make_float2(acc[8 + 2 * q], acc[8 + 2 * q + 1]));
    }
    uint4* dst = g_MA4 + (size_t)warp * 64 + lane * 2;
    dst[0] = o0; dst[1] = o1;

    h_epilogue(warp, lane, acc, __ldg(hopwise + 1), out);
}

// ---------------- prop hops + fused H-update ---------------------------------
__global__ void __launch_bounds__(256) k_prop(const uint4* __restrict__ Msrc,
                                              uint4* __restrict__ Mdst, int writeM,
                                              int hop, const float* __restrict__ hopwise,
                                              float* __restrict__ out) {
    int warp = (blockIdx.x * blockDim.x + threadIdx.x) >> 5;
    if (warp >= NN) return;
    int lane = threadIdx.x & 31;

    float acc[16];
#pragma unroll
    for (int t = 0; t < 16; t++) acc[t] = 0.0f;

    int beg = g_ptr[warp], end = g_ptr[warp + 1];
    int p = beg;
    for (; p + 4 <= end; p += 4) {
        int r0 = g_src[p], r1 = g_src[p + 1], r2 = g_src[p + 2], r3 = g_src[p + 3];
        float w0 = g_wt[p], w1 = g_wt[p + 1], w2 = g_wt[p + 2], w3 = g_wt[p + 3];
        const uint4* m0 = Msrc + (size_t)r0 * 64 + lane * 2;
        const uint4* m1 = Msrc + (size_t)r1 * 64 + lane * 2;
        const uint4* m2 = Msrc + (size_t)r2 * 64 + lane * 2;
        const uint4* m3 = Msrc + (size_t)r3 * 64 + lane * 2;
        uint4 A0 = m0[0], A1 = m0[1];
        uint4 B0 = m1[0], B1 = m1[1];
        uint4 C0 = m2[0], C1 = m2[1];
        uint4 D0 = m3[0], D1 = m3[1];
        acc8(acc, A0, w0); acc8(acc + 8, A1, w0);
        acc8(acc, B0, w1); acc8(acc + 8, B1, w1);
        acc8(acc, C0, w2); acc8(acc + 8, C1, w2);
        acc8(acc, D0, w3); acc8(acc + 8, D1, w3);
    }
    for (; p < end; p++) {
        int r0 = g_src[p];
        float w0 = g_wt[p];
        const uint4* m0 = Msrc + (size_t)r0 * 64 + lane * 2;
        uint4 A0 = m0[0], A1 = m0[1];
        acc8(acc, A0, w0); acc8(acc + 8, A1, w0);
    }

    if (writeM) {
        uint4 o0, o1;
        __half2* ho0 = (__half2*)&o0;
        __half2* ho1 = (__half2*)&o1;
#pragma unroll
        for (int q = 0; q < 4; q++) {
            ho0[q] = __float22half2_rn(make_float2(acc[2 * q], acc[2 * q + 1]));
            ho1[q] = __float22half2_rn(make_float2(acc[8 + 2 * q], acc[8 + 2 * q + 1]));
        }
        uint4* dst = Mdst + (size_t)warp * 64 + lane * 2;
        dst[0] = o0; dst[1] = o1;
    }

    h_epilogue(warp, lane, acc, __ldg(hopwise + hop), out);
}

// ---------------- launch -----------------------------------------------------
extern "C" void kernel_launch(void* const* d_in, const int* in_sizes, int n_in,
                              void* d_out, int out_size) {
    const float* x  = (const float*)d_in[0];
    const int*   ei = (const int*)d_in[1];
    const float* ef = (const float*)d_in[2];
    const float* ew = (const float*)d_in[3];
    const float* Wq = (const float*)d_in[4];
    const float* bq = (const float*)d_in[5];
    const float* Wk = (const float*)d_in[6];
    const float* bk = (const float*)d_in[7];
    const float* Wv = (const float*)d_in[8];
    const float* bv = (const float*)d_in[9];
    const float* hw = (const float*)d_in[10];
    const int* row = ei;
    const int* col = ei + EE;
    float* out = (float*)d_out;

    uint4 *dMA, *dMB;
    cudaGetSymbolAddress((void**)&dMA, g_MA4);
    cudaGetSymbolAddress((void**)&dMB, g_MB4);

    k_zero<<<(NN + 255) / 256, 256>>>();
    k_count<<<(EE + 255) / 256, 256>>>(col);
    k_scan<<<1, 1024>>>();
    k_place<<<(EE + 255) / 256, 256>>>(col);
    k_sortbuckets<<<(NN + 255) / 256, 256>>>();
    k_gather<<<(EE + 255) / 256, 256>>>(row, col, ew);

    k_qkv<<<NN / 16, 256>>>(x, Wq, bq, Wk, bk, Wv, bv, hw, out);

    k_hop0<<<(NN * 32) / 256, 256>>>(ef, hw, out);                 // -> MA, out += hw[1]*H
    k_prop<<<(NN * 32) / 256, 256>>>(dMA, dMB, 1, 2, hw, out);     // MA -> MB, out += hw[2]*H
    k_prop<<<(NN * 32) / 256, 256>>>(dMB, dMA, 0, 3, hw, out);     // MB read-only, out += hw[3]*H
}